// round 13
// baseline (speedup 1.0000x reference)
#include <cuda_runtime.h>

#define NEG_SLOPE 0.2f

// x: [B=8, C=256, H=128, W=128] f32. row = b*C+c. group == batch.
static constexpr int NROWS = 2048;
static constexpr int ROW_ELEMS = 16384;          // H*W
static constexpr int C = 256;
static constexpr int CS = 16;

static constexpr int GROUP_ROWS = 256;             // 1 batch = 16.75 MB
static constexpr int NGROUPS = NROWS / GROUP_ROWS; // 8

static constexpr int GAP_CTAS = GROUP_ROWS;        // 256, bids [0, 256)
static constexpr int SCALE_CTAS = 2 * GROUP_ROWS;  // 512 half-row CTAs, bids [256, 768)
static constexpr int GRID = GAP_CTAS + SCALE_CTAS; // 768

__device__ float g_y[NROWS];   // pooled means

struct f8 { float a0,a1,a2,a3,a4,a5,a6,a7; };

__device__ __forceinline__ f8 ldg_evict_last_32B(const void* p) {
    unsigned long long d0, d1, d2, d3;
    asm("ld.global.L2::evict_last.v4.b64 {%0,%1,%2,%3}, [%4];"
        : "=l"(d0), "=l"(d1), "=l"(d2), "=l"(d3) : "l"(p));
    f8 r;
    r.a0 = __uint_as_float((unsigned)(d0)); r.a1 = __uint_as_float((unsigned)(d0 >> 32));
    r.a2 = __uint_as_float((unsigned)(d1)); r.a3 = __uint_as_float((unsigned)(d1 >> 32));
    r.a4 = __uint_as_float((unsigned)(d2)); r.a5 = __uint_as_float((unsigned)(d2 >> 32));
    r.a6 = __uint_as_float((unsigned)(d3)); r.a7 = __uint_as_float((unsigned)(d3 >> 32));
    return r;
}

__device__ __forceinline__ f8 ldg_32B(const void* p) {
    unsigned long long d0, d1, d2, d3;
    asm("ld.global.v4.b64 {%0,%1,%2,%3}, [%4];"
        : "=l"(d0), "=l"(d1), "=l"(d2), "=l"(d3) : "l"(p));
    f8 r;
    r.a0 = __uint_as_float((unsigned)(d0)); r.a1 = __uint_as_float((unsigned)(d0 >> 32));
    r.a2 = __uint_as_float((unsigned)(d1)); r.a3 = __uint_as_float((unsigned)(d1 >> 32));
    r.a4 = __uint_as_float((unsigned)(d2)); r.a5 = __uint_as_float((unsigned)(d2 >> 32));
    r.a6 = __uint_as_float((unsigned)(d3)); r.a7 = __uint_as_float((unsigned)(d3 >> 32));
    return r;
}

__device__ __forceinline__ void stg_evict_first_32B(void* p, const f8& v) {
    unsigned long long d0 = ((unsigned long long)__float_as_uint(v.a1) << 32) | __float_as_uint(v.a0);
    unsigned long long d1 = ((unsigned long long)__float_as_uint(v.a3) << 32) | __float_as_uint(v.a2);
    unsigned long long d2 = ((unsigned long long)__float_as_uint(v.a5) << 32) | __float_as_uint(v.a4);
    unsigned long long d3 = ((unsigned long long)__float_as_uint(v.a7) << 32) | __float_as_uint(v.a6);
    asm volatile("st.global.L2::evict_first.v4.b64 [%0], {%1,%2,%3,%4};"
                 :: "l"(p), "l"(d0), "l"(d1), "l"(d2), "l"(d3) : "memory");
}

// ---------------------------------------------------------------------------
// Pipelined step kernel with PDL (1-batch groups, gap-first bid order):
//   bid in [0, 256):   gap one row of group step (no wait -> starts streaming
//                      during predecessor's drain; evict_last install)
//   bid in [256, 768): scale HALF-row of group (step-1) (waits on prev grid)
// ---------------------------------------------------------------------------
__global__ __launch_bounds__(256) void pipe_kernel(const float* __restrict__ x,
                                                   const float* __restrict__ w1,
                                                   const float* __restrict__ b1,
                                                   const float* __restrict__ w2,
                                                   const float* __restrict__ b2,
                                                   float* __restrict__ out,
                                                   int step) {
    asm volatile("griddepcontrol.launch_dependents;");

    const int tid = threadIdx.x;
    const int bid = blockIdx.x;

    if (bid < GAP_CTAS) {
        // ---------------- GAP role: pool one row of group `step` ----------------
        if (step >= NGROUPS) return;
        const int row = step * GROUP_ROWS + bid;
        const char* __restrict__ xr =
            reinterpret_cast<const char*>(x) + (size_t)row * (size_t)ROW_ELEMS * 4;

        float s = 0.f;
#pragma unroll
        for (int i = 0; i < ROW_ELEMS / 8 / 256; i++) {   // 8 iters of 32B
            f8 v = ldg_evict_last_32B(xr + (size_t)(tid + i * 256) * 32);
            s += ((v.a0 + v.a1) + (v.a2 + v.a3)) + ((v.a4 + v.a5) + (v.a6 + v.a7));
        }
#pragma unroll
        for (int off = 16; off > 0; off >>= 1)
            s += __shfl_xor_sync(0xFFFFFFFF, s, off);

        __shared__ float warp_sums[8];
        if ((tid & 31) == 0) warp_sums[tid >> 5] = s;
        __syncthreads();
        if (tid == 0) {
            float tot = 0.f;
#pragma unroll
            for (int w = 0; w < 8; w++) tot += warp_sums[w];
            g_y[row] = tot * (1.0f / ROW_ELEMS);
        }
        return;
    }

    // ------------- SCALE role: gate + scale half a row of group `step-1` -------------
    if (step < 1) return;

    // wait for the previous step's grid (its gap wrote g_y for group step-1)
    asm volatile("griddepcontrol.wait;" ::: "memory");

    const int sbid = bid - GAP_CTAS;           // 0..511
    const int row = (step - 1) * GROUP_ROWS + (sbid >> 1);
    const int half = sbid & 1;
    const int b = row / C;
    const int c = row % C;

    __shared__ float sh_y1[CS];
    __shared__ float sh_gate;
    {
        const int s_idx = tid >> 4;   // 0..15
        const int cc = tid & 15;      // 0..15
        const float* __restrict__ yb = g_y + b * C;
        const float* __restrict__ wrow = w1 + s_idx * C;
        float part = 0.f;
#pragma unroll
        for (int k = 0; k < C / 16; k++) {
            const int cidx = cc + k * 16;
            part += wrow[cidx] * yb[cidx];
        }
#pragma unroll
        for (int off = 8; off > 0; off >>= 1)
            part += __shfl_down_sync(0xFFFFFFFF, part, off, 16);
        if (cc == 0) {
            part += b1[s_idx];
            sh_y1[s_idx] = (part >= 0.f) ? part : NEG_SLOPE * part;
        }
    }
    __syncthreads();
    if (tid == 0) {
        const float* __restrict__ w2row = w2 + c * CS;
        float acc = b2[c];
#pragma unroll
        for (int s = 0; s < CS; s++) acc += w2row[s] * sh_y1[s];
        sh_gate = 1.0f / (1.0f + __expf(-acc));
    }
    __syncthreads();
    const float g = sh_gate;

    const size_t base_bytes =
        ((size_t)row * ROW_ELEMS + (size_t)half * (ROW_ELEMS / 2)) * 4;
    const char* __restrict__ xr = reinterpret_cast<const char*>(x) + base_bytes;
    char* __restrict__ orow = reinterpret_cast<char*>(out) + base_bytes;
#pragma unroll
    for (int i = 0; i < ROW_ELEMS / 2 / 8 / 256; i++) {   // 4 iters of 32B
        const size_t off = (size_t)(tid + i * 256) * 32;
        f8 v = ldg_32B(xr + off);   // L2 hit: pinned by previous step's gap
        v.a0 *= g; v.a1 *= g; v.a2 *= g; v.a3 *= g;
        v.a4 *= g; v.a5 *= g; v.a6 *= g; v.a7 *= g;
        stg_evict_first_32B(orow + off, v);
    }
}

extern "C" void kernel_launch(void* const* d_in, const int* in_sizes, int n_in,
                              void* d_out, int out_size) {
    const float* x  = (const float*)d_in[0];
    const float* w1 = (const float*)d_in[1];
    const float* b1 = (const float*)d_in[2];
    const float* w2 = (const float*)d_in[3];
    const float* b2 = (const float*)d_in[4];
    float* out = (float*)d_out;

    cudaLaunchAttribute attr[1];
    attr[0].id = cudaLaunchAttributeProgrammaticStreamSerialization;
    attr[0].val.programmaticStreamSerializationAllowed = 1;

    cudaLaunchConfig_t cfg = {};
    cfg.gridDim = dim3(GRID, 1, 1);
    cfg.blockDim = dim3(256, 1, 1);
    cfg.dynamicSmemBytes = 0;
    cfg.stream = 0;
    cfg.attrs = attr;
    cfg.numAttrs = 1;

    // steps: 0 = gap(g0); 1..7 = scale(g-1)+gap(g); 8 = scale(g7)
    for (int step = 0; step <= NGROUPS; step++) {
        cudaLaunchKernelEx(&cfg, pipe_kernel, x, w1, b1, w2, b2, out, step);
    }
}

// round 14
// speedup vs baseline: 1.0296x; 1.0296x over previous
#include <cuda_runtime.h>

#define NEG_SLOPE 0.2f

// x: [B=8, C=256, H=128, W=128] f32. row = b*C+c.
static constexpr int NROWS = 2048;
static constexpr int ROW_ELEMS = 16384;          // H*W
static constexpr int C = 256;
static constexpr int CS = 16;

static constexpr int GROUP_ROWS = 512;             // 2 batches = 33.5 MB
static constexpr int NGROUPS = NROWS / GROUP_ROWS; // 4

static constexpr int GAP_CTAS = GROUP_ROWS;        // 512, bids [0, 512)  (no wait -> placed first)
static constexpr int SCALE_CTAS = 2 * GROUP_ROWS;  // 1024 half-row CTAs, bids [512, 1536)
static constexpr int GRID = GAP_CTAS + SCALE_CTAS; // 1536

__device__ float g_y[NROWS];   // pooled means

struct f8 { float a0,a1,a2,a3,a4,a5,a6,a7; };

__device__ __forceinline__ f8 ldg_evict_last_32B(const void* p) {
    unsigned long long d0, d1, d2, d3;
    asm("ld.global.L2::evict_last.v4.b64 {%0,%1,%2,%3}, [%4];"
        : "=l"(d0), "=l"(d1), "=l"(d2), "=l"(d3) : "l"(p));
    f8 r;
    r.a0 = __uint_as_float((unsigned)(d0)); r.a1 = __uint_as_float((unsigned)(d0 >> 32));
    r.a2 = __uint_as_float((unsigned)(d1)); r.a3 = __uint_as_float((unsigned)(d1 >> 32));
    r.a4 = __uint_as_float((unsigned)(d2)); r.a5 = __uint_as_float((unsigned)(d2 >> 32));
    r.a6 = __uint_as_float((unsigned)(d3)); r.a7 = __uint_as_float((unsigned)(d3 >> 32));
    return r;
}

__device__ __forceinline__ f8 ldg_32B(const void* p) {
    unsigned long long d0, d1, d2, d3;
    asm("ld.global.v4.b64 {%0,%1,%2,%3}, [%4];"
        : "=l"(d0), "=l"(d1), "=l"(d2), "=l"(d3) : "l"(p));
    f8 r;
    r.a0 = __uint_as_float((unsigned)(d0)); r.a1 = __uint_as_float((unsigned)(d0 >> 32));
    r.a2 = __uint_as_float((unsigned)(d1)); r.a3 = __uint_as_float((unsigned)(d1 >> 32));
    r.a4 = __uint_as_float((unsigned)(d2)); r.a5 = __uint_as_float((unsigned)(d2 >> 32));
    r.a6 = __uint_as_float((unsigned)(d3)); r.a7 = __uint_as_float((unsigned)(d3 >> 32));
    return r;
}

__device__ __forceinline__ void stg_evict_first_32B(void* p, const f8& v) {
    unsigned long long d0 = ((unsigned long long)__float_as_uint(v.a1) << 32) | __float_as_uint(v.a0);
    unsigned long long d1 = ((unsigned long long)__float_as_uint(v.a3) << 32) | __float_as_uint(v.a2);
    unsigned long long d2 = ((unsigned long long)__float_as_uint(v.a5) << 32) | __float_as_uint(v.a4);
    unsigned long long d3 = ((unsigned long long)__float_as_uint(v.a7) << 32) | __float_as_uint(v.a6);
    asm volatile("st.global.L2::evict_first.v4.b64 [%0], {%1,%2,%3,%4};"
                 :: "l"(p), "l"(d0), "l"(d1), "l"(d2), "l"(d3) : "memory");
}

// ---------------------------------------------------------------------------
// Pipelined step kernel with PDL (R12 config, gap-first bid order):
//   bid in [0, 512):    gap one row of group step — no wait, starts streaming
//                       during the predecessor's drain (evict_last install)
//   bid in [512, 1536): scale HALF-row of group (step-1) — waits on prev grid
// ---------------------------------------------------------------------------
__global__ __launch_bounds__(256) void pipe_kernel(const float* __restrict__ x,
                                                   const float* __restrict__ w1,
                                                   const float* __restrict__ b1,
                                                   const float* __restrict__ w2,
                                                   const float* __restrict__ b2,
                                                   float* __restrict__ out,
                                                   int step) {
    asm volatile("griddepcontrol.launch_dependents;");

    const int tid = threadIdx.x;
    const int bid = blockIdx.x;

    if (bid < GAP_CTAS) {
        // ---------------- GAP role: pool one row of group `step` ----------------
        if (step >= NGROUPS) return;
        const int row = step * GROUP_ROWS + bid;
        const char* __restrict__ xr =
            reinterpret_cast<const char*>(x) + (size_t)row * (size_t)ROW_ELEMS * 4;

        float s = 0.f;
#pragma unroll
        for (int i = 0; i < ROW_ELEMS / 8 / 256; i++) {   // 8 iters of 32B
            f8 v = ldg_evict_last_32B(xr + (size_t)(tid + i * 256) * 32);
            s += ((v.a0 + v.a1) + (v.a2 + v.a3)) + ((v.a4 + v.a5) + (v.a6 + v.a7));
        }
#pragma unroll
        for (int off = 16; off > 0; off >>= 1)
            s += __shfl_xor_sync(0xFFFFFFFF, s, off);

        __shared__ float warp_sums[8];
        if ((tid & 31) == 0) warp_sums[tid >> 5] = s;
        __syncthreads();
        if (tid == 0) {
            float tot = 0.f;
#pragma unroll
            for (int w = 0; w < 8; w++) tot += warp_sums[w];
            g_y[row] = tot * (1.0f / ROW_ELEMS);
        }
        return;
    }

    // ------------- SCALE role: gate + scale half a row of group `step-1` -------------
    if (step < 1) return;

    // wait for the previous step's grid (its gap wrote g_y for group step-1)
    asm volatile("griddepcontrol.wait;" ::: "memory");

    const int sbid = bid - GAP_CTAS;           // 0..1023
    const int row = (step - 1) * GROUP_ROWS + (sbid >> 1);
    const int half = sbid & 1;
    const int b = row / C;
    const int c = row % C;

    __shared__ float sh_y1[CS];
    __shared__ float sh_gate;
    {
        const int s_idx = tid >> 4;   // 0..15
        const int cc = tid & 15;      // 0..15
        const float* __restrict__ yb = g_y + b * C;
        const float* __restrict__ wrow = w1 + s_idx * C;
        float part = 0.f;
#pragma unroll
        for (int k = 0; k < C / 16; k++) {
            const int cidx = cc + k * 16;
            part += wrow[cidx] * yb[cidx];
        }
#pragma unroll
        for (int off = 8; off > 0; off >>= 1)
            part += __shfl_down_sync(0xFFFFFFFF, part, off, 16);
        if (cc == 0) {
            part += b1[s_idx];
            sh_y1[s_idx] = (part >= 0.f) ? part : NEG_SLOPE * part;
        }
    }
    __syncthreads();
    if (tid == 0) {
        const float* __restrict__ w2row = w2 + c * CS;
        float acc = b2[c];
#pragma unroll
        for (int s = 0; s < CS; s++) acc += w2row[s] * sh_y1[s];
        sh_gate = 1.0f / (1.0f + __expf(-acc));
    }
    __syncthreads();
    const float g = sh_gate;

    const size_t base_bytes =
        ((size_t)row * ROW_ELEMS + (size_t)half * (ROW_ELEMS / 2)) * 4;
    const char* __restrict__ xr = reinterpret_cast<const char*>(x) + base_bytes;
    char* __restrict__ orow = reinterpret_cast<char*>(out) + base_bytes;
#pragma unroll
    for (int i = 0; i < ROW_ELEMS / 2 / 8 / 256; i++) {   // 4 iters of 32B
        const size_t off = (size_t)(tid + i * 256) * 32;
        f8 v = ldg_32B(xr + off);   // mostly L2 hit: pinned by previous step's gap
        v.a0 *= g; v.a1 *= g; v.a2 *= g; v.a3 *= g;
        v.a4 *= g; v.a5 *= g; v.a6 *= g; v.a7 *= g;
        stg_evict_first_32B(orow + off, v);
    }
}

extern "C" void kernel_launch(void* const* d_in, const int* in_sizes, int n_in,
                              void* d_out, int out_size) {
    const float* x  = (const float*)d_in[0];
    const float* w1 = (const float*)d_in[1];
    const float* b1 = (const float*)d_in[2];
    const float* w2 = (const float*)d_in[3];
    const float* b2 = (const float*)d_in[4];
    float* out = (float*)d_out;

    cudaLaunchAttribute attr[1];
    attr[0].id = cudaLaunchAttributeProgrammaticStreamSerialization;
    attr[0].val.programmaticStreamSerializationAllowed = 1;

    cudaLaunchConfig_t cfg = {};
    cfg.gridDim = dim3(GRID, 1, 1);
    cfg.blockDim = dim3(256, 1, 1);
    cfg.dynamicSmemBytes = 0;
    cfg.stream = 0;
    cfg.attrs = attr;
    cfg.numAttrs = 1;

    // steps: 0 = gap(g0); 1..3 = scale(g-1)+gap(g); 4 = scale(g3)
    for (int step = 0; step <= NGROUPS; step++) {
        cudaLaunchKernelEx(&cfg, pipe_kernel, x, w1, b1, w2, b2, out, step);
    }
}

// round 15
// speedup vs baseline: 1.2252x; 1.1899x over previous
#include <cuda_runtime.h>

#define NEG_SLOPE 0.2f

// x: [B=8, C=256, H=128, W=128] f32. row = b*C+c.
static constexpr int NROWS = 2048;
static constexpr int ROW_ELEMS = 16384;          // H*W
static constexpr int C = 256;
static constexpr int CS = 16;

static constexpr int GROUP_ROWS = 512;             // 2 batches = 33.5 MB
static constexpr int NGROUPS = NROWS / GROUP_ROWS; // 4

static constexpr int SCALE_CTAS = 2 * GROUP_ROWS;  // 1024 half-row CTAs, bids [0, 1024)
static constexpr int GAP_CTAS = GROUP_ROWS;        // 512, bids [1024, 1536)  (R12 order)
static constexpr int GRID = SCALE_CTAS + GAP_CTAS; // 1536

__device__ float g_y[NROWS];   // pooled means

struct f8 { float a0,a1,a2,a3,a4,a5,a6,a7; };

__device__ __forceinline__ f8 ldg_evict_last_32B(const void* p) {
    unsigned long long d0, d1, d2, d3;
    asm("ld.global.L2::evict_last.v4.b64 {%0,%1,%2,%3}, [%4];"
        : "=l"(d0), "=l"(d1), "=l"(d2), "=l"(d3) : "l"(p));
    f8 r;
    r.a0 = __uint_as_float((unsigned)(d0)); r.a1 = __uint_as_float((unsigned)(d0 >> 32));
    r.a2 = __uint_as_float((unsigned)(d1)); r.a3 = __uint_as_float((unsigned)(d1 >> 32));
    r.a4 = __uint_as_float((unsigned)(d2)); r.a5 = __uint_as_float((unsigned)(d2 >> 32));
    r.a6 = __uint_as_float((unsigned)(d3)); r.a7 = __uint_as_float((unsigned)(d3 >> 32));
    return r;
}

__device__ __forceinline__ f8 ldg_32B(const void* p) {
    unsigned long long d0, d1, d2, d3;
    asm("ld.global.v4.b64 {%0,%1,%2,%3}, [%4];"
        : "=l"(d0), "=l"(d1), "=l"(d2), "=l"(d3) : "l"(p));
    f8 r;
    r.a0 = __uint_as_float((unsigned)(d0)); r.a1 = __uint_as_float((unsigned)(d0 >> 32));
    r.a2 = __uint_as_float((unsigned)(d1)); r.a3 = __uint_as_float((unsigned)(d1 >> 32));
    r.a4 = __uint_as_float((unsigned)(d2)); r.a5 = __uint_as_float((unsigned)(d2 >> 32));
    r.a6 = __uint_as_float((unsigned)(d3)); r.a7 = __uint_as_float((unsigned)(d3 >> 32));
    return r;
}

__device__ __forceinline__ void stg_evict_first_32B(void* p, const f8& v) {
    unsigned long long d0 = ((unsigned long long)__float_as_uint(v.a1) << 32) | __float_as_uint(v.a0);
    unsigned long long d1 = ((unsigned long long)__float_as_uint(v.a3) << 32) | __float_as_uint(v.a2);
    unsigned long long d2 = ((unsigned long long)__float_as_uint(v.a5) << 32) | __float_as_uint(v.a4);
    unsigned long long d3 = ((unsigned long long)__float_as_uint(v.a7) << 32) | __float_as_uint(v.a6);
    asm volatile("st.global.L2::evict_first.v4.b64 [%0], {%1,%2,%3,%4};"
                 :: "l"(p), "l"(d0), "l"(d1), "l"(d2), "l"(d3) : "memory");
}

// ---------------------------------------------------------------------------
// Pipelined step kernel with PDL (R12 bid order) + pre-wait x prefetch:
//   bid in [0, 1024):    scale HALF-row of group (step-1). Issues ALL x reads
//                        (read-only input, pinned in L2 by the previous step's
//                        gap) BEFORE griddepcontrol.wait — the read stream
//                        overlaps the predecessor's drain; after the wait only
//                        FC + writes remain.
//   bid in [1024, 1536): gap one row of group step (evict_last install).
// ---------------------------------------------------------------------------
__global__ __launch_bounds__(256) void pipe_kernel(const float* __restrict__ x,
                                                   const float* __restrict__ w1,
                                                   const float* __restrict__ b1,
                                                   const float* __restrict__ w2,
                                                   const float* __restrict__ b2,
                                                   float* __restrict__ out,
                                                   int step) {
    asm volatile("griddepcontrol.launch_dependents;");

    const int tid = threadIdx.x;
    const int bid = blockIdx.x;

    if (bid >= SCALE_CTAS) {
        // ---------------- GAP role: pool one row of group `step` ----------------
        if (step >= NGROUPS) return;
        const int row = step * GROUP_ROWS + (bid - SCALE_CTAS);
        const char* __restrict__ xr =
            reinterpret_cast<const char*>(x) + (size_t)row * (size_t)ROW_ELEMS * 4;

        float s = 0.f;
#pragma unroll
        for (int i = 0; i < ROW_ELEMS / 8 / 256; i++) {   // 8 iters of 32B
            f8 v = ldg_evict_last_32B(xr + (size_t)(tid + i * 256) * 32);
            s += ((v.a0 + v.a1) + (v.a2 + v.a3)) + ((v.a4 + v.a5) + (v.a6 + v.a7));
        }
#pragma unroll
        for (int off = 16; off > 0; off >>= 1)
            s += __shfl_xor_sync(0xFFFFFFFF, s, off);

        __shared__ float warp_sums[8];
        if ((tid & 31) == 0) warp_sums[tid >> 5] = s;
        __syncthreads();
        if (tid == 0) {
            float tot = 0.f;
#pragma unroll
            for (int w = 0; w < 8; w++) tot += warp_sums[w];
            g_y[row] = tot * (1.0f / ROW_ELEMS);
        }
        return;
    }

    // ------------- SCALE role: gate + scale half a row of group `step-1` -------------
    if (step < 1) return;

    const int sbid = bid;                      // 0..1023
    const int row = (step - 1) * GROUP_ROWS + (sbid >> 1);
    const int half = sbid & 1;
    const int b = row / C;
    const int c = row % C;

    const size_t base_bytes =
        ((size_t)row * ROW_ELEMS + (size_t)half * (ROW_ELEMS / 2)) * 4;
    const char* __restrict__ xr = reinterpret_cast<const char*>(x) + base_bytes;
    char* __restrict__ orow = reinterpret_cast<char*>(out) + base_bytes;

    // ---- PREFETCH all x data BEFORE the wait (x is a read-only input; its
    // values cannot depend on the previous grid). 4 x 32B per thread. ----
    f8 v[4];
#pragma unroll
    for (int i = 0; i < 4; i++)
        v[i] = ldg_32B(xr + (size_t)(tid + i * 256) * 32);

    // wait for the previous step's grid (its gap wrote g_y for group step-1)
    asm volatile("griddepcontrol.wait;" ::: "memory");

    __shared__ float sh_y1[CS];
    __shared__ float sh_gate;
    {
        const int s_idx = tid >> 4;   // 0..15
        const int cc = tid & 15;      // 0..15
        const float* __restrict__ yb = g_y + b * C;
        const float* __restrict__ wrow = w1 + s_idx * C;
        float part = 0.f;
#pragma unroll
        for (int k = 0; k < C / 16; k++) {
            const int cidx = cc + k * 16;
            part += wrow[cidx] * yb[cidx];
        }
#pragma unroll
        for (int off = 8; off > 0; off >>= 1)
            part += __shfl_down_sync(0xFFFFFFFF, part, off, 16);
        if (cc == 0) {
            part += b1[s_idx];
            sh_y1[s_idx] = (part >= 0.f) ? part : NEG_SLOPE * part;
        }
    }
    __syncthreads();
    if (tid == 0) {
        const float* __restrict__ w2row = w2 + c * CS;
        float acc = b2[c];
#pragma unroll
        for (int s = 0; s < CS; s++) acc += w2row[s] * sh_y1[s];
        sh_gate = 1.0f / (1.0f + __expf(-acc));
    }
    __syncthreads();
    const float g = sh_gate;

#pragma unroll
    for (int i = 0; i < 4; i++) {
        const size_t off = (size_t)(tid + i * 256) * 32;
        f8 t = v[i];
        t.a0 *= g; t.a1 *= g; t.a2 *= g; t.a3 *= g;
        t.a4 *= g; t.a5 *= g; t.a6 *= g; t.a7 *= g;
        stg_evict_first_32B(orow + off, t);
    }
}

extern "C" void kernel_launch(void* const* d_in, const int* in_sizes, int n_in,
                              void* d_out, int out_size) {
    const float* x  = (const float*)d_in[0];
    const float* w1 = (const float*)d_in[1];
    const float* b1 = (const float*)d_in[2];
    const float* w2 = (const float*)d_in[3];
    const float* b2 = (const float*)d_in[4];
    float* out = (float*)d_out;

    cudaLaunchAttribute attr[1];
    attr[0].id = cudaLaunchAttributeProgrammaticStreamSerialization;
    attr[0].val.programmaticStreamSerializationAllowed = 1;

    cudaLaunchConfig_t cfg = {};
    cfg.gridDim = dim3(GRID, 1, 1);
    cfg.blockDim = dim3(256, 1, 1);
    cfg.dynamicSmemBytes = 0;
    cfg.stream = 0;
    cfg.attrs = attr;
    cfg.numAttrs = 1;

    // steps: 0 = gap(g0); 1..3 = scale(g-1)+gap(g); 4 = scale(g3)
    for (int step = 0; step <= NGROUPS; step++) {
        cudaLaunchKernelEx(&cfg, pipe_kernel, x, w1, b1, w2, b2, out, step);
    }
}